// round 16
// baseline (speedup 1.0000x reference)
#include <cuda_runtime.h>
#include <cuda_bf16.h>
#include <cuda_fp16.h>
#include <math.h>
#include <stdint.h>

#define N_NODES 30000
#define N_EDGES 480000
#define NHEAD   4
#define HD      512
#define OUTF    128
#define NEG_SLOPE 0.2f
#define BN_EPS  1e-5f
#define BN_BLOCKS 256
#define SCAN_NB 118
#define NROWB   235          // ceil(30000/128)

// ---------------- scratch ----------------
__device__ __align__(16) unsigned short g_h16[N_NODES * HD];
__device__ float g_rst[N_NODES * HD];
__device__ float g_el[N_NODES * NHEAD];
__device__ float g_er[N_NODES * NHEAD];
__device__ float g_P[8 * 128];
__device__ int   g_deg[N_NODES];
__device__ int   g_cursor[N_NODES];
__device__ int   g_ptr[N_NODES + 1];
__device__ int   g_srcs[N_EDGES];
__device__ int   g_blocksum[SCAN_NB];
__device__ int   g_blockoff[SCAN_NB];
__device__ float g_psum[BN_BLOCKS * HD];
__device__ float g_psq[BN_BLOCKS * HD];
__device__ float g_scale[HD];
__device__ float g_shift[HD];
__device__ int   g_bn_ticket;
__device__ __align__(16) unsigned short g_WT1h[1024 * 128];   // fp16 [n][k]
__device__ __align__(16) unsigned short g_WT2h[128 * 512];    // fp16 [n][k]

// ---------------- helpers ----------------
__device__ __forceinline__ uint32_t f2h2(float lo, float hi) {
    __half2 h = __floats2half2_rn(lo, hi);
    return *(uint32_t*)&h;
}
__device__ __forceinline__ float2 h2f(uint32_t u) {
    return __half22float2(*(__half2*)&u);
}
__device__ __forceinline__ unsigned short f2h_us(float x) {
    __half h = __float2half_rn(x);
    return *(unsigned short*)&h;
}
__device__ __forceinline__ void mma_f16(float* c, uint32_t a0, uint32_t a1,
                                        uint32_t a2, uint32_t a3,
                                        uint32_t b0, uint32_t b1) {
    asm volatile(
        "mma.sync.aligned.m16n8k16.row.col.f32.f16.f16.f32 "
        "{%0,%1,%2,%3}, {%4,%5,%6,%7}, {%8,%9}, {%0,%1,%2,%3};"
        : "+f"(c[0]), "+f"(c[1]), "+f"(c[2]), "+f"(c[3])
        : "r"(a0), "r"(a1), "r"(a2), "r"(a3), "r"(b0), "r"(b1));
}

// ---------------- fused prep ----------------
__global__ __launch_bounds__(256) void prep_kernel(
    const float* __restrict__ Wfc, const float* __restrict__ Wres,
    const float* __restrict__ Wout, const float* __restrict__ attn_l,
    const float* __restrict__ attn_r) {
    int b = blockIdx.x;
    int tid = threadIdx.x;
    if (b == 0 && tid == 0) g_bn_ticket = 0;
    if (b < SCAN_NB) {
        int i = b * 256 + tid;
        if (i < N_NODES) g_deg[i] = 0;
        return;
    }
    b -= SCAN_NB;
    if (b < 128) {
        __shared__ float t[32][33];
        int k0 = (b & 3) * 32;
        int n0 = (b >> 2) * 32;
        int tx = tid & 31, ty = tid >> 5;
        const float* W = (n0 < 512) ? Wfc : Wres;
        int nn0 = (n0 < 512) ? n0 : n0 - 512;
#pragma unroll
        for (int i = 0; i < 32; i += 8)
            t[ty + i][tx] = W[(k0 + ty + i) * 512 + nn0 + tx];
        __syncthreads();
#pragma unroll
        for (int i = 0; i < 32; i += 8) {
            float v = t[tx][ty + i];
            int n = n0 + ty + i, k = k0 + tx;
            g_WT1h[n * 128 + k] = f2h_us(v);
        }
        return;
    }
    b -= 128;
    if (b < 64) {
        __shared__ float t2[32][33];
        int k0 = (b & 15) * 32;
        int n0 = (b >> 4) * 32;
        int tx = tid & 31, ty = tid >> 5;
#pragma unroll
        for (int i = 0; i < 32; i += 8)
            t2[ty + i][tx] = Wout[(k0 + ty + i) * 128 + n0 + tx];
        __syncthreads();
#pragma unroll
        for (int i = 0; i < 32; i += 8) {
            float v = t2[tx][ty + i];
            int n = n0 + ty + i, k = k0 + tx;
            g_WT2h[n * 512 + k] = f2h_us(v);
        }
        return;
    }
    b -= 64;
    if (tid >= 128) return;
    int h = b & 3;
    const float* av = ((b < 4) ? attn_l : attn_r) + h * 128;
    const float* wr = Wfc + tid * HD + h * 128;
    float s = 0.f;
#pragma unroll
    for (int d4 = 0; d4 < 32; d4++) {
        float4 w = *(const float4*)(wr + d4 * 4);
        float4 a = *(const float4*)(av + d4 * 4);
        s += w.x * a.x + w.y * a.y + w.z * a.z + w.w * a.w;
    }
    g_P[b * 128 + tid] = s;
}

__global__ __launch_bounds__(256) void elr_kernel(const float* __restrict__ feat) {
    __shared__ float Ps[8][128];
    int t = threadIdx.x;
    for (int i = t; i < 1024; i += 256) Ps[i >> 7][i & 127] = g_P[i];
    __syncthreads();
    int n = blockIdx.x * 8 + (t >> 5);
    int lane = t & 31;
    if (n >= N_NODES) return;
    float4 f = *(const float4*)(feat + n * 128 + lane * 4);
    float s[8];
#pragma unroll
    for (int j = 0; j < 8; j++) {
        const float* p = &Ps[j][lane * 4];
        s[j] = f.x * p[0] + f.y * p[1] + f.z * p[2] + f.w * p[3];
    }
#pragma unroll
    for (int o = 16; o; o >>= 1)
#pragma unroll
        for (int j = 0; j < 8; j++) s[j] += __shfl_xor_sync(0xffffffffu, s[j], o);
    if (lane < 4) {
        g_el[n * 4 + lane] = s[lane];
        g_er[n * 4 + lane] = s[lane + 4];
    }
}

// ---------------- CSR build ----------------
__global__ void hist_kernel(const int* __restrict__ dst) {
    int e = blockIdx.x * blockDim.x + threadIdx.x;
    if (e < N_EDGES) atomicAdd(&g_deg[dst[e]], 1);
}

__global__ void scan1_kernel() {
    __shared__ int wsum[8];
    int t = threadIdx.x, b = blockIdx.x;
    int idx = b * 256 + t;
    int lane = t & 31, wid = t >> 5;
    int v = (idx < N_NODES) ? g_deg[idx] : 0;
    int x = v;
#pragma unroll
    for (int o = 1; o < 32; o <<= 1) {
        int y = __shfl_up_sync(0xffffffffu, x, o);
        if (lane >= o) x += y;
    }
    if (lane == 31) wsum[wid] = x;
    __syncthreads();
    if (t == 0) {
        int run = 0;
#pragma unroll
        for (int i = 0; i < 8; i++) { int tmp = wsum[i]; wsum[i] = run; run += tmp; }
        g_blocksum[b] = run;
    }
    __syncthreads();
    int incl = x + wsum[wid];
    if (idx < N_NODES) g_ptr[idx + 1] = incl;
}

__global__ void scan2_kernel() {
    __shared__ int ws[4];
    int t = threadIdx.x;
    int lane = t & 31, w = t >> 5;
    int v = (t < SCAN_NB) ? g_blocksum[t] : 0;
    int x = v;
#pragma unroll
    for (int o = 1; o < 32; o <<= 1) {
        int y = __shfl_up_sync(0xffffffffu, x, o);
        if (lane >= o) x += y;
    }
    if (lane == 31) ws[w] = x;
    __syncthreads();
    if (t == 0) {
        int run = 0;
#pragma unroll
        for (int i = 0; i < 4; i++) { int tmp = ws[i]; ws[i] = run; run += tmp; }
    }
    __syncthreads();
    if (t < SCAN_NB) g_blockoff[t] = x + ws[w] - v;
}

__global__ void scan3_kernel() {
    int t = threadIdx.x, b = blockIdx.x;
    int idx = b * 256 + t;
    if (idx >= N_NODES) return;
    int off = g_blockoff[b];
    int incl = g_ptr[idx + 1] + off;
    g_ptr[idx + 1] = incl;
    g_cursor[idx] = incl - g_deg[idx];
    if (idx == 0) g_ptr[0] = 0;
}

__global__ void scatter_kernel(const int* __restrict__ src,
                               const int* __restrict__ dst) {
    int e = blockIdx.x * blockDim.x + threadIdx.x;
    if (e < N_EDGES) {
        int p = atomicAdd(&g_cursor[dst[e]], 1);
        g_srcs[p] = src[e];
    }
}

// ---------------- GEMM1: BM=128 BN=64, occ 4, one wave ----------------
#define KS1 136
#define KS1_32 68
#define SMEM_G1 ((128 + 64) * KS1 * 2)   // 52224 bytes
#define SMEM_G2 (2 * 128 * KS1 * 2)      // 69632 bytes

__global__ __launch_bounds__(256, 4) void gemm1_mma(const float* __restrict__ feat,
                                                    const float* __restrict__ biasg) {
    extern __shared__ unsigned short sm[];
    unsigned short* Ah = sm;
    unsigned short* Bh = Ah + 128 * KS1;
    const int tid = threadIdx.x;
    const int warp = tid >> 5, lane = tid & 31;
    const int wm = warp >> 1, wn = warp & 1;
    const int g = lane >> 2, t = lane & 3;
    const int row0 = blockIdx.y * 128;
    const int half = blockIdx.x;

    for (int idx = tid; idx < 4096; idx += 256) {
        int r = idx >> 5, k4 = idx & 31;
        int gr = row0 + r;
        float4 f = make_float4(0.f, 0.f, 0.f, 0.f);
        if (gr < N_NODES) f = *(const float4*)(feat + gr * 128 + k4 * 4);
        *(uint2*)(Ah + r * KS1 + k4 * 4) = make_uint2(f2h2(f.x, f.y), f2h2(f.z, f.w));
    }

    const uint32_t* Ah32 = (const uint32_t*)Ah;
    const uint32_t* Bh32 = (const uint32_t*)Bh;

    for (int i = 0; i < 8; i++) {
        int n0 = (half * 8 + i) * 64;
        for (int idx = tid; idx < 2048; idx += 256) {
            int r = idx >> 5, k4 = idx & 31;
            *(uint2*)(Bh + r * KS1 + k4 * 4) =
                *(const uint2*)(g_WT1h + (n0 + r) * 128 + k4 * 4);
        }
        __syncthreads();

        float c[2][4][4];
#pragma unroll
        for (int a = 0; a < 2; a++)
#pragma unroll
            for (int bq = 0; bq < 4; bq++)
#pragma unroll
                for (int q = 0; q < 4; q++) c[a][bq][q] = 0.f;

#pragma unroll
        for (int ks = 0; ks < 8; ks++) {
            int kb = ks * 8;
            uint32_t ah[2][4], bh[4][2];
#pragma unroll
            for (int rb = 0; rb < 2; rb++) {
                int base = (wm * 32 + rb * 16 + g) * KS1_32 + kb + t;
                ah[rb][0] = Ah32[base];             ah[rb][1] = Ah32[base + 8 * KS1_32];
                ah[rb][2] = Ah32[base + 4];         ah[rb][3] = Ah32[base + 8 * KS1_32 + 4];
            }
#pragma unroll
            for (int nb = 0; nb < 4; nb++) {
                int base = (wn * 32 + nb * 8 + g) * KS1_32 + kb + t;
                bh[nb][0] = Bh32[base];  bh[nb][1] = Bh32[base + 4];
            }
#pragma unroll
            for (int rb = 0; rb < 2; rb++)
#pragma unroll
                for (int nb = 0; nb < 4; nb++)
                    mma_f16(c[rb][nb], ah[rb][0], ah[rb][1], ah[rb][2], ah[rb][3],
                            bh[nb][0], bh[nb][1]);
        }
#pragma unroll
        for (int rb = 0; rb < 2; rb++) {
            int gr0 = row0 + wm * 32 + rb * 16 + g;
#pragma unroll
            for (int nb = 0; nb < 4; nb++) {
                int col = n0 + wn * 32 + nb * 8 + 2 * t;
                float* cc = c[rb][nb];
                if (col < 512) {
                    if (gr0 < N_NODES)
                        *(uint32_t*)(g_h16 + gr0 * HD + col) = f2h2(cc[0], cc[1]);
                    if (gr0 + 8 < N_NODES)
                        *(uint32_t*)(g_h16 + (gr0 + 8) * HD + col) = f2h2(cc[2], cc[3]);
                } else {
                    int cb = col - 512;
                    float2 bv = *(const float2*)(biasg + cb);
                    if (gr0 < N_NODES)
                        *(float2*)(g_rst + gr0 * HD + cb) =
                            make_float2(cc[0] + bv.x, cc[1] + bv.y);
                    if (gr0 + 8 < N_NODES)
                        *(float2*)(g_rst + (gr0 + 8) * HD + cb) =
                            make_float2(cc[2] + bv.x, cc[3] + bv.y);
                }
            }
        }
        __syncthreads();
    }
}

// ---------------- aggregation: one warp per (node, head) ----------------
__global__ __launch_bounds__(256) void agg_kernel() {
    int gw = blockIdx.x * 8 + (threadIdx.x >> 5);   // warp over N_NODES*4
    int lane = threadIdx.x & 31;
    if (gw >= N_NODES * 4) return;
    int v = gw >> 2, h = gw & 3;
    int start = g_ptr[v], end = g_ptr[v + 1];
    if (start == end) return;                       // keep residual+bias only
    float er = g_er[v * 4 + h];

    float4 a0 = make_float4(0.f, 0.f, 0.f, 0.f);
    float d0 = 0.f;

    const unsigned short* hbase = g_h16 + h * 128 + lane * 4;
    const float* elbase = g_el + h;
    int j = start;
#pragma unroll 1
    for (; j + 1 < end; j += 2) {
        int sA = g_srcs[j], sB = g_srcs[j + 1];
        float elA = elbase[sA * 4];
        float elB = elbase[sB * 4];
        uint2 qA = *(const uint2*)(hbase + sA * HD);
        uint2 qB = *(const uint2*)(hbase + sB * HD);

        float e0 = elA + er; e0 = (e0 > 0.f) ? e0 : NEG_SLOPE * e0;
        float wA = __expf(e0);
        e0 = elB + er; e0 = (e0 > 0.f) ? e0 : NEG_SLOPE * e0;
        float wB = __expf(e0);
        d0 += wA;
        d0 += wB;

        float2 p;
        p = h2f(qA.x); a0.x += wA * p.x; a0.y += wA * p.y;
        p = h2f(qA.y); a0.z += wA * p.x; a0.w += wA * p.y;
        p = h2f(qB.x); a0.x += wB * p.x; a0.y += wB * p.y;
        p = h2f(qB.y); a0.z += wB * p.x; a0.w += wB * p.y;
    }
    if (j < end) {
        int s = g_srcs[j];
        float el = elbase[s * 4];
        uint2 q0 = *(const uint2*)(hbase + s * HD);
        float e0 = el + er; e0 = (e0 > 0.f) ? e0 : NEG_SLOPE * e0;
        float w0 = __expf(e0);
        d0 += w0;
        float2 p;
        p = h2f(q0.x); a0.x += w0 * p.x; a0.y += w0 * p.y;
        p = h2f(q0.y); a0.z += w0 * p.x; a0.w += w0 * p.y;
    }
    float i0 = 1.f / d0;
    float* o = g_rst + v * HD + h * 128 + lane * 4;
    float4 c0 = *(float4*)(o);
    c0.x += a0.x * i0; c0.y += a0.y * i0; c0.z += a0.z * i0; c0.w += a0.w * i0;
    *(float4*)(o) = c0;
}

// ---------------- fused BatchNorm ----------------
__global__ void bn_kernel(const float* __restrict__ gamma,
                          const float* __restrict__ beta) {
    int c = threadIdx.x;
    float s = 0.f, q = 0.f;
    for (int r = blockIdx.x; r < N_NODES; r += gridDim.x) {
        float x = g_rst[r * HD + c];
        s += x;
        q += x * x;
    }
    g_psum[blockIdx.x * HD + c] = s;
    g_psq[blockIdx.x * HD + c] = q;
    __threadfence();
    __shared__ int is_last;
    if (c == 0) is_last = (atomicAdd(&g_bn_ticket, 1) == gridDim.x - 1);
    __syncthreads();
    if (!is_last) return;
    float S = 0.f, Q = 0.f;
    for (int b = 0; b < BN_BLOCKS; b++) {
        S += g_psum[b * HD + c];
        Q += g_psq[b * HD + c];
    }
    float mu = S / (float)N_NODES;
    float var = Q / (float)N_NODES - mu * mu;
    float rstd = rsqrtf(var + BN_EPS);
    float sc = gamma[c] * rstd;
    g_scale[c] = sc;
    g_shift[c] = beta[c] - mu * sc;
}

// ---------------- GEMM2 (single-term fp16 mma.sync, BK=128, occ 3) ----------
__global__ __launch_bounds__(256, 3) void gemm2_mma(const float* __restrict__ bout,
                                                    float* __restrict__ out) {
    extern __shared__ unsigned short sm[];
    unsigned short* Ah = sm;
    unsigned short* Bh = Ah + 128 * KS1;
    const int tid = threadIdx.x;
    const int warp = tid >> 5, lane = tid & 31;
    const int wm = warp >> 2, wn = warp & 3;
    const int g = lane >> 2, t = lane & 3;
    const int row0 = blockIdx.x * 128;

    const uint32_t* Ah32 = (const uint32_t*)Ah;
    const uint32_t* Bh32 = (const uint32_t*)Bh;

    float c[4][4][4];
#pragma unroll
    for (int a = 0; a < 4; a++)
#pragma unroll
        for (int bq = 0; bq < 4; bq++)
#pragma unroll
            for (int q = 0; q < 4; q++) c[a][bq][q] = 0.f;

    for (int kc = 0; kc < 4; kc++) {
        int k0 = kc * 128;
        for (int idx = tid; idx < 4096; idx += 256) {
            int r = idx >> 5, k4 = idx & 31;
            int gr = row0 + r;
            int col = k0 + k4 * 4;
            float4 v = make_float4(0.f, 0.f, 0.f, 0.f);
            if (gr < N_NODES) {
                float4 x = *(const float4*)(g_rst + gr * HD + col);
                float4 sc = *(const float4*)(g_scale + col);
                float4 sh = *(const float4*)(g_shift + col);
                v.x = fmaxf(sc.x * x.x + sh.x, 0.f);
                v.y = fmaxf(sc.y * x.y + sh.y, 0.f);
                v.z = fmaxf(sc.z * x.z + sh.z, 0.f);
                v.w = fmaxf(sc.w * x.w + sh.w, 0.f);
            }
            *(uint2*)(Ah + r * KS1 + k4 * 4) = make_uint2(f2h2(v.x, v.y), f2h2(v.z, v.w));
            *(uint2*)(Bh + r * KS1 + k4 * 4) = *(const uint2*)(g_WT2h + r * 512 + col);
        }
        __syncthreads();
#pragma unroll
        for (int ks = 0; ks < 8; ks++) {
            int kb = ks * 8;
            uint32_t ah[4][4], bh[4][2];
#pragma unroll
            for (int rb = 0; rb < 4; rb++) {
                int base = (wm * 64 + rb * 16 + g) * KS1_32 + kb + t;
                ah[rb][0] = Ah32[base];             ah[rb][1] = Ah32[base + 8 * KS1_32];
                ah[rb][2] = Ah32[base + 4];         ah[rb][3] = Ah32[base + 8 * KS1_32 + 4];
            }
#pragma unroll
            for (int nb = 0; nb < 4; nb++) {
                int base = (wn * 32 + nb * 8 + g) * KS1_32 + kb + t;
                bh[nb][0] = Bh32[base];  bh[nb][1] = Bh32[base + 4];
            }
#pragma unroll
            for (int rb = 0; rb < 4; rb++)
#pragma unroll
                for (int nb = 0; nb < 4; nb++)
                    mma_f16(c[rb][nb], ah[rb][0], ah[rb][1], ah[rb][2], ah[rb][3],
                            bh[nb][0], bh[nb][1]);
        }
        __syncthreads();
    }
#pragma unroll
    for (int rb = 0; rb < 4; rb++) {
        int gr0 = row0 + wm * 64 + rb * 16 + g;
#pragma unroll
        for (int nb = 0; nb < 4; nb++) {
            int col = wn * 32 + nb * 8 + 2 * t;
            float* cc = c[rb][nb];
            float2 bv = *(const float2*)(bout + col);
            if (gr0 < N_NODES)
                *(float2*)(out + gr0 * OUTF + col) =
                    make_float2(cc[0] + bv.x, cc[1] + bv.y);
            if (gr0 + 8 < N_NODES)
                *(float2*)(out + (gr0 + 8) * OUTF + col) =
                    make_float2(cc[2] + bv.x, cc[3] + bv.y);
        }
    }
}

// ---------------- launch (fork/join overlap) ----------------
extern "C" void kernel_launch(void* const* d_in, const int* in_sizes, int n_in,
                              void* d_out, int out_size) {
    const float* feat    = (const float*)d_in[0];
    const int*   src     = (const int*)d_in[1];
    const int*   dst     = (const int*)d_in[2];
    const float* Wfc     = (const float*)d_in[3];
    const float* attn_l  = (const float*)d_in[4];
    const float* attn_r  = (const float*)d_in[5];
    const float* Wres    = (const float*)d_in[6];
    const float* biasg   = (const float*)d_in[7];
    const float* gamma   = (const float*)d_in[8];
    const float* beta    = (const float*)d_in[9];
    const float* Wout    = (const float*)d_in[10];
    const float* bout    = (const float*)d_in[11];
    float* out = (float*)d_out;

    static cudaStream_t sB = nullptr;
    static cudaEvent_t evRoot = nullptr, evCsr = nullptr;
    if (sB == nullptr) {
        cudaStreamCreateWithFlags(&sB, cudaStreamNonBlocking);
        cudaEventCreateWithFlags(&evRoot, cudaEventDisableTiming);
        cudaEventCreateWithFlags(&evCsr, cudaEventDisableTiming);
        cudaFuncSetAttribute(gemm1_mma, cudaFuncAttributeMaxDynamicSharedMemorySize, SMEM_G1);
        cudaFuncSetAttribute(gemm2_mma, cudaFuncAttributeMaxDynamicSharedMemorySize, SMEM_G2);
    }

    prep_kernel<<<SCAN_NB + 128 + 64 + 8, 256>>>(Wfc, Wres, Wout, attn_l, attn_r);
    cudaEventRecord(evRoot, 0);

    cudaStreamWaitEvent(sB, evRoot, 0);
    elr_kernel<<<(N_NODES + 7) / 8, 256, 0, sB>>>(feat);
    hist_kernel<<<(N_EDGES + 255) / 256, 256, 0, sB>>>(dst);
    scan1_kernel<<<SCAN_NB, 256, 0, sB>>>();
    scan2_kernel<<<1, 128, 0, sB>>>();
    scan3_kernel<<<SCAN_NB, 256, 0, sB>>>();
    scatter_kernel<<<(N_EDGES + 255) / 256, 256, 0, sB>>>(src, dst);
    cudaEventRecord(evCsr, sB);

    gemm1_mma<<<dim3(2, NROWB), 256, SMEM_G1>>>(feat, biasg);

    cudaStreamWaitEvent(0, evCsr, 0);
    agg_kernel<<<(N_NODES * 4 + 7) / 8, 256>>>();
    bn_kernel<<<BN_BLOCKS, HD>>>(gamma, beta);
    gemm2_mma<<<NROWB, 256, SMEM_G2>>>(bout, out);
}

// round 17
// speedup vs baseline: 1.1328x; 1.1328x over previous
#include <cuda_runtime.h>
#include <cuda_bf16.h>
#include <cuda_fp16.h>
#include <math.h>
#include <stdint.h>

#define N_NODES 30000
#define N_EDGES 480000
#define NHEAD   4
#define HD      512
#define OUTF    128
#define NEG_SLOPE 0.2f
#define BN_EPS  1e-5f
#define BN_BLOCKS 256
#define SCAN_NB 118
#define NROWB   235          // ceil(30000/128)

// ---------------- scratch ----------------
__device__ __align__(16) unsigned short g_h16[N_NODES * HD];
__device__ float g_rst[N_NODES * HD];
__device__ float g_el[N_NODES * NHEAD];
__device__ float g_er[N_NODES * NHEAD];
__device__ float g_P[8 * 128];
__device__ int   g_deg[N_NODES];
__device__ int   g_cursor[N_NODES];
__device__ int   g_ptr[N_NODES + 1];
__device__ int   g_srcs[N_EDGES];
__device__ int   g_blocksum[SCAN_NB];
__device__ int   g_blockoff[SCAN_NB];
__device__ float g_psum[BN_BLOCKS * HD];
__device__ float g_psq[BN_BLOCKS * HD];
__device__ float g_scale[HD];
__device__ float g_shift[HD];
__device__ int   g_bn_ticket;
__device__ __align__(16) unsigned short g_WT1h[1024 * 128];   // fp16 [n][k]
__device__ __align__(16) unsigned short g_WT2h[128 * 512];    // fp16 [n][k]

// ---------------- helpers ----------------
__device__ __forceinline__ uint32_t f2h2(float lo, float hi) {
    __half2 h = __floats2half2_rn(lo, hi);
    return *(uint32_t*)&h;
}
__device__ __forceinline__ float2 h2f(uint32_t u) {
    return __half22float2(*(__half2*)&u);
}
__device__ __forceinline__ unsigned short f2h_us(float x) {
    __half h = __float2half_rn(x);
    return *(unsigned short*)&h;
}
__device__ __forceinline__ void mma_f16(float* c, uint32_t a0, uint32_t a1,
                                        uint32_t a2, uint32_t a3,
                                        uint32_t b0, uint32_t b1) {
    asm volatile(
        "mma.sync.aligned.m16n8k16.row.col.f32.f16.f16.f32 "
        "{%0,%1,%2,%3}, {%4,%5,%6,%7}, {%8,%9}, {%0,%1,%2,%3};"
        : "+f"(c[0]), "+f"(c[1]), "+f"(c[2]), "+f"(c[3])
        : "r"(a0), "r"(a1), "r"(a2), "r"(a3), "r"(b0), "r"(b1));
}

// ---------------- fused prep ----------------
__global__ __launch_bounds__(256) void prep_kernel(
    const float* __restrict__ Wfc, const float* __restrict__ Wres,
    const float* __restrict__ Wout, const float* __restrict__ attn_l,
    const float* __restrict__ attn_r) {
    int b = blockIdx.x;
    int tid = threadIdx.x;
    if (b == 0 && tid == 0) g_bn_ticket = 0;
    if (b < SCAN_NB) {
        int i = b * 256 + tid;
        if (i < N_NODES) g_deg[i] = 0;
        return;
    }
    b -= SCAN_NB;
    if (b < 128) {
        __shared__ float t[32][33];
        int k0 = (b & 3) * 32;
        int n0 = (b >> 2) * 32;
        int tx = tid & 31, ty = tid >> 5;
        const float* W = (n0 < 512) ? Wfc : Wres;
        int nn0 = (n0 < 512) ? n0 : n0 - 512;
#pragma unroll
        for (int i = 0; i < 32; i += 8)
            t[ty + i][tx] = W[(k0 + ty + i) * 512 + nn0 + tx];
        __syncthreads();
#pragma unroll
        for (int i = 0; i < 32; i += 8) {
            float v = t[tx][ty + i];
            int n = n0 + ty + i, k = k0 + tx;
            g_WT1h[n * 128 + k] = f2h_us(v);
        }
        return;
    }
    b -= 128;
    if (b < 64) {
        __shared__ float t2[32][33];
        int k0 = (b & 15) * 32;
        int n0 = (b >> 4) * 32;
        int tx = tid & 31, ty = tid >> 5;
#pragma unroll
        for (int i = 0; i < 32; i += 8)
            t2[ty + i][tx] = Wout[(k0 + ty + i) * 128 + n0 + tx];
        __syncthreads();
#pragma unroll
        for (int i = 0; i < 32; i += 8) {
            float v = t2[tx][ty + i];
            int n = n0 + ty + i, k = k0 + tx;
            g_WT2h[n * 512 + k] = f2h_us(v);
        }
        return;
    }
    b -= 64;
    if (tid >= 128) return;
    int h = b & 3;
    const float* av = ((b < 4) ? attn_l : attn_r) + h * 128;
    const float* wr = Wfc + tid * HD + h * 128;
    float s = 0.f;
#pragma unroll
    for (int d4 = 0; d4 < 32; d4++) {
        float4 w = *(const float4*)(wr + d4 * 4);
        float4 a = *(const float4*)(av + d4 * 4);
        s += w.x * a.x + w.y * a.y + w.z * a.z + w.w * a.w;
    }
    g_P[b * 128 + tid] = s;
}

__global__ __launch_bounds__(256) void elr_kernel(const float* __restrict__ feat) {
    __shared__ float Ps[8][128];
    int t = threadIdx.x;
    for (int i = t; i < 1024; i += 256) Ps[i >> 7][i & 127] = g_P[i];
    __syncthreads();
    int n = blockIdx.x * 8 + (t >> 5);
    int lane = t & 31;
    if (n >= N_NODES) return;
    float4 f = *(const float4*)(feat + n * 128 + lane * 4);
    float s[8];
#pragma unroll
    for (int j = 0; j < 8; j++) {
        const float* p = &Ps[j][lane * 4];
        s[j] = f.x * p[0] + f.y * p[1] + f.z * p[2] + f.w * p[3];
    }
#pragma unroll
    for (int o = 16; o; o >>= 1)
#pragma unroll
        for (int j = 0; j < 8; j++) s[j] += __shfl_xor_sync(0xffffffffu, s[j], o);
    if (lane < 4) {
        g_el[n * 4 + lane] = s[lane];
        g_er[n * 4 + lane] = s[lane + 4];
    }
}

// ---------------- CSR build ----------------
__global__ void hist_kernel(const int* __restrict__ dst) {
    int e = blockIdx.x * blockDim.x + threadIdx.x;
    if (e < N_EDGES) atomicAdd(&g_deg[dst[e]], 1);
}

__global__ void scan1_kernel() {
    __shared__ int wsum[8];
    int t = threadIdx.x, b = blockIdx.x;
    int idx = b * 256 + t;
    int lane = t & 31, wid = t >> 5;
    int v = (idx < N_NODES) ? g_deg[idx] : 0;
    int x = v;
#pragma unroll
    for (int o = 1; o < 32; o <<= 1) {
        int y = __shfl_up_sync(0xffffffffu, x, o);
        if (lane >= o) x += y;
    }
    if (lane == 31) wsum[wid] = x;
    __syncthreads();
    if (t == 0) {
        int run = 0;
#pragma unroll
        for (int i = 0; i < 8; i++) { int tmp = wsum[i]; wsum[i] = run; run += tmp; }
        g_blocksum[b] = run;
    }
    __syncthreads();
    int incl = x + wsum[wid];
    if (idx < N_NODES) g_ptr[idx + 1] = incl;
}

__global__ void scan2_kernel() {
    __shared__ int ws[4];
    int t = threadIdx.x;
    int lane = t & 31, w = t >> 5;
    int v = (t < SCAN_NB) ? g_blocksum[t] : 0;
    int x = v;
#pragma unroll
    for (int o = 1; o < 32; o <<= 1) {
        int y = __shfl_up_sync(0xffffffffu, x, o);
        if (lane >= o) x += y;
    }
    if (lane == 31) ws[w] = x;
    __syncthreads();
    if (t == 0) {
        int run = 0;
#pragma unroll
        for (int i = 0; i < 4; i++) { int tmp = ws[i]; ws[i] = run; run += tmp; }
    }
    __syncthreads();
    if (t < SCAN_NB) g_blockoff[t] = x + ws[w] - v;
}

__global__ void scan3_kernel() {
    int t = threadIdx.x, b = blockIdx.x;
    int idx = b * 256 + t;
    if (idx >= N_NODES) return;
    int off = g_blockoff[b];
    int incl = g_ptr[idx + 1] + off;
    g_ptr[idx + 1] = incl;
    g_cursor[idx] = incl - g_deg[idx];
    if (idx == 0) g_ptr[0] = 0;
}

__global__ void scatter_kernel(const int* __restrict__ src,
                               const int* __restrict__ dst) {
    int e = blockIdx.x * blockDim.x + threadIdx.x;
    if (e < N_EDGES) {
        int p = atomicAdd(&g_cursor[dst[e]], 1);
        g_srcs[p] = src[e];
    }
}

// ---------------- GEMM1: BM=128 BN=64, occ 4, one wave ----------------
#define KS1 136
#define KS1_32 68
#define SMEM_G1 ((128 + 64) * KS1 * 2)   // 52224 bytes
#define SMEM_G2 (2 * 128 * KS1 * 2)      // 69632 bytes

__global__ __launch_bounds__(256, 4) void gemm1_mma(const float* __restrict__ feat,
                                                    const float* __restrict__ biasg) {
    extern __shared__ unsigned short sm[];
    unsigned short* Ah = sm;
    unsigned short* Bh = Ah + 128 * KS1;
    const int tid = threadIdx.x;
    const int warp = tid >> 5, lane = tid & 31;
    const int wm = warp >> 1, wn = warp & 1;
    const int g = lane >> 2, t = lane & 3;
    const int row0 = blockIdx.y * 128;
    const int half = blockIdx.x;

    for (int idx = tid; idx < 4096; idx += 256) {
        int r = idx >> 5, k4 = idx & 31;
        int gr = row0 + r;
        float4 f = make_float4(0.f, 0.f, 0.f, 0.f);
        if (gr < N_NODES) f = *(const float4*)(feat + gr * 128 + k4 * 4);
        *(uint2*)(Ah + r * KS1 + k4 * 4) = make_uint2(f2h2(f.x, f.y), f2h2(f.z, f.w));
    }

    const uint32_t* Ah32 = (const uint32_t*)Ah;
    const uint32_t* Bh32 = (const uint32_t*)Bh;

    for (int i = 0; i < 8; i++) {
        int n0 = (half * 8 + i) * 64;
        for (int idx = tid; idx < 2048; idx += 256) {
            int r = idx >> 5, k4 = idx & 31;
            *(uint2*)(Bh + r * KS1 + k4 * 4) =
                *(const uint2*)(g_WT1h + (n0 + r) * 128 + k4 * 4);
        }
        __syncthreads();

        float c[2][4][4];
#pragma unroll
        for (int a = 0; a < 2; a++)
#pragma unroll
            for (int bq = 0; bq < 4; bq++)
#pragma unroll
                for (int q = 0; q < 4; q++) c[a][bq][q] = 0.f;

#pragma unroll
        for (int ks = 0; ks < 8; ks++) {
            int kb = ks * 8;
            uint32_t ah[2][4], bh[4][2];
#pragma unroll
            for (int rb = 0; rb < 2; rb++) {
                int base = (wm * 32 + rb * 16 + g) * KS1_32 + kb + t;
                ah[rb][0] = Ah32[base];             ah[rb][1] = Ah32[base + 8 * KS1_32];
                ah[rb][2] = Ah32[base + 4];         ah[rb][3] = Ah32[base + 8 * KS1_32 + 4];
            }
#pragma unroll
            for (int nb = 0; nb < 4; nb++) {
                int base = (wn * 32 + nb * 8 + g) * KS1_32 + kb + t;
                bh[nb][0] = Bh32[base];  bh[nb][1] = Bh32[base + 4];
            }
#pragma unroll
            for (int rb = 0; rb < 2; rb++)
#pragma unroll
                for (int nb = 0; nb < 4; nb++)
                    mma_f16(c[rb][nb], ah[rb][0], ah[rb][1], ah[rb][2], ah[rb][3],
                            bh[nb][0], bh[nb][1]);
        }
#pragma unroll
        for (int rb = 0; rb < 2; rb++) {
            int gr0 = row0 + wm * 32 + rb * 16 + g;
#pragma unroll
            for (int nb = 0; nb < 4; nb++) {
                int col = n0 + wn * 32 + nb * 8 + 2 * t;
                float* cc = c[rb][nb];
                if (col < 512) {
                    if (gr0 < N_NODES)
                        *(uint32_t*)(g_h16 + gr0 * HD + col) = f2h2(cc[0], cc[1]);
                    if (gr0 + 8 < N_NODES)
                        *(uint32_t*)(g_h16 + (gr0 + 8) * HD + col) = f2h2(cc[2], cc[3]);
                } else {
                    int cb = col - 512;
                    float2 bv = *(const float2*)(biasg + cb);
                    if (gr0 < N_NODES)
                        *(float2*)(g_rst + gr0 * HD + cb) =
                            make_float2(cc[0] + bv.x, cc[1] + bv.y);
                    if (gr0 + 8 < N_NODES)
                        *(float2*)(g_rst + (gr0 + 8) * HD + cb) =
                            make_float2(cc[2] + bv.x, cc[3] + bv.y);
                }
            }
        }
        __syncthreads();
    }
}

// ---------------- aggregation: one warp per (node, head-pair) ---------------
__global__ __launch_bounds__(256) void agg_kernel() {
    int gw = blockIdx.x * 8 + (threadIdx.x >> 5);   // warp over N_NODES*2
    int lane = threadIdx.x & 31;
    if (gw >= N_NODES * 2) return;
    int v = gw >> 1, hp = gw & 1;                   // heads 2*hp, 2*hp+1
    int start = g_ptr[v], end = g_ptr[v + 1];
    if (start == end) return;                       // keep residual+bias only
    float2 er = *(const float2*)(g_er + v * 4 + hp * 2);

    float4 a0 = make_float4(0.f, 0.f, 0.f, 0.f);
    float4 a1 = a0;
    float d0 = 0.f, d1 = 0.f;

    const unsigned short* hbase = g_h16 + hp * 256 + lane * 4;
    int j = start;
#pragma unroll 1
    for (; j + 1 < end; j += 2) {
        int sA = g_srcs[j], sB = g_srcs[j + 1];
        float2 elA = *(const float2*)(g_el + sA * 4 + hp * 2);
        float2 elB = *(const float2*)(g_el + sB * 4 + hp * 2);
        const unsigned short* hpA = hbase + sA * HD;
        const unsigned short* hpB = hbase + sB * HD;
        uint2 qA0 = *(const uint2*)(hpA);
        uint2 qA1 = *(const uint2*)(hpA + 128);
        uint2 qB0 = *(const uint2*)(hpB);
        uint2 qB1 = *(const uint2*)(hpB + 128);

        float e0 = elA.x + er.x; e0 = (e0 > 0.f) ? e0 : NEG_SLOPE * e0;
        float e1 = elA.y + er.y; e1 = (e1 > 0.f) ? e1 : NEG_SLOPE * e1;
        float wA0 = __expf(e0), wA1 = __expf(e1);
        e0 = elB.x + er.x; e0 = (e0 > 0.f) ? e0 : NEG_SLOPE * e0;
        e1 = elB.y + er.y; e1 = (e1 > 0.f) ? e1 : NEG_SLOPE * e1;
        float wB0 = __expf(e0), wB1 = __expf(e1);
        d0 += wA0; d1 += wA1;
        d0 += wB0; d1 += wB1;

        float2 p;
        p = h2f(qA0.x); a0.x += wA0 * p.x; a0.y += wA0 * p.y;
        p = h2f(qA0.y); a0.z += wA0 * p.x; a0.w += wA0 * p.y;
        p = h2f(qA1.x); a1.x += wA1 * p.x; a1.y += wA1 * p.y;
        p = h2f(qA1.y); a1.z += wA1 * p.x; a1.w += wA1 * p.y;
        p = h2f(qB0.x); a0.x += wB0 * p.x; a0.y += wB0 * p.y;
        p = h2f(qB0.y); a0.z += wB0 * p.x; a0.w += wB0 * p.y;
        p = h2f(qB1.x); a1.x += wB1 * p.x; a1.y += wB1 * p.y;
        p = h2f(qB1.y); a1.z += wB1 * p.x; a1.w += wB1 * p.y;
    }
    if (j < end) {
        int s = g_srcs[j];
        float2 el = *(const float2*)(g_el + s * 4 + hp * 2);
        const unsigned short* hps = hbase + s * HD;
        uint2 q0 = *(const uint2*)(hps);
        uint2 q1 = *(const uint2*)(hps + 128);
        float e0 = el.x + er.x; e0 = (e0 > 0.f) ? e0 : NEG_SLOPE * e0;
        float e1 = el.y + er.y; e1 = (e1 > 0.f) ? e1 : NEG_SLOPE * e1;
        float w0 = __expf(e0), w1 = __expf(e1);
        d0 += w0; d1 += w1;
        float2 p;
        p = h2f(q0.x); a0.x += w0 * p.x; a0.y += w0 * p.y;
        p = h2f(q0.y); a0.z += w0 * p.x; a0.w += w0 * p.y;
        p = h2f(q1.x); a1.x += w1 * p.x; a1.y += w1 * p.y;
        p = h2f(q1.y); a1.z += w1 * p.x; a1.w += w1 * p.y;
    }
    float i0 = 1.f / d0, i1 = 1.f / d1;
    float* o = g_rst + v * HD + hp * 256 + lane * 4;
    float4 c0 = *(float4*)(o);
    float4 c1 = *(float4*)(o + 128);
    c0.x += a0.x * i0; c0.y += a0.y * i0; c0.z += a0.z * i0; c0.w += a0.w * i0;
    c1.x += a1.x * i1; c1.y += a1.y * i1; c1.z += a1.z * i1; c1.w += a1.w * i1;
    *(float4*)(o)       = c0;
    *(float4*)(o + 128) = c1;
}

// ---------------- fused BatchNorm ----------------
__global__ void bn_kernel(const float* __restrict__ gamma,
                          const float* __restrict__ beta) {
    int c = threadIdx.x;
    float s = 0.f, q = 0.f;
    for (int r = blockIdx.x; r < N_NODES; r += gridDim.x) {
        float x = g_rst[r * HD + c];
        s += x;
        q += x * x;
    }
    g_psum[blockIdx.x * HD + c] = s;
    g_psq[blockIdx.x * HD + c] = q;
    __threadfence();
    __shared__ int is_last;
    if (c == 0) is_last = (atomicAdd(&g_bn_ticket, 1) == gridDim.x - 1);
    __syncthreads();
    if (!is_last) return;
    float S = 0.f, Q = 0.f;
    for (int b = 0; b < BN_BLOCKS; b++) {
        S += g_psum[b * HD + c];
        Q += g_psq[b * HD + c];
    }
    float mu = S / (float)N_NODES;
    float var = Q / (float)N_NODES - mu * mu;
    float rstd = rsqrtf(var + BN_EPS);
    float sc = gamma[c] * rstd;
    g_scale[c] = sc;
    g_shift[c] = beta[c] - mu * sc;
}

// ---------------- GEMM2 (single-term fp16 mma.sync, BK=128) ----------------
__global__ __launch_bounds__(256) void gemm2_mma(const float* __restrict__ bout,
                                                 float* __restrict__ out) {
    extern __shared__ unsigned short sm[];
    unsigned short* Ah = sm;
    unsigned short* Bh = Ah + 128 * KS1;
    const int tid = threadIdx.x;
    const int warp = tid >> 5, lane = tid & 31;
    const int wm = warp >> 2, wn = warp & 3;
    const int g = lane >> 2, t = lane & 3;
    const int row0 = blockIdx.x * 128;

    const uint32_t* Ah32 = (const uint32_t*)Ah;
    const uint32_t* Bh32 = (const uint32_t*)Bh;

    float c[4][4][4];
#pragma unroll
    for (int a = 0; a < 4; a++)
#pragma unroll
        for (int bq = 0; bq < 4; bq++)
#pragma unroll
            for (int q = 0; q < 4; q++) c[a][bq][q] = 0.f;

    for (int kc = 0; kc < 4; kc++) {
        int k0 = kc * 128;
        for (int idx = tid; idx < 4096; idx += 256) {
            int r = idx >> 5, k4 = idx & 31;
            int gr = row0 + r;
            int col = k0 + k4 * 4;
            float4 v = make_float4(0.f, 0.f, 0.f, 0.f);
            if (gr < N_NODES) {
                float4 x = *(const float4*)(g_rst + gr * HD + col);
                float4 sc = *(const float4*)(g_scale + col);
                float4 sh = *(const float4*)(g_shift + col);
                v.x = fmaxf(sc.x * x.x + sh.x, 0.f);
                v.y = fmaxf(sc.y * x.y + sh.y, 0.f);
                v.z = fmaxf(sc.z * x.z + sh.z, 0.f);
                v.w = fmaxf(sc.w * x.w + sh.w, 0.f);
            }
            *(uint2*)(Ah + r * KS1 + k4 * 4) = make_uint2(f2h2(v.x, v.y), f2h2(v.z, v.w));
            *(uint2*)(Bh + r * KS1 + k4 * 4) = *(const uint2*)(g_WT2h + r * 512 + col);
        }
        __syncthreads();
#pragma unroll
        for (int ks = 0; ks < 8; ks++) {
            int kb = ks * 8;
            uint32_t ah[4][4], bh[4][2];
#pragma unroll
            for (int rb = 0; rb < 4; rb++) {
                int base = (wm * 64 + rb * 16 + g) * KS1_32 + kb + t;
                ah[rb][0] = Ah32[base];             ah[rb][1] = Ah32[base + 8 * KS1_32];
                ah[rb][2] = Ah32[base + 4];         ah[rb][3] = Ah32[base + 8 * KS1_32 + 4];
            }
#pragma unroll
            for (int nb = 0; nb < 4; nb++) {
                int base = (wn * 32 + nb * 8 + g) * KS1_32 + kb + t;
                bh[nb][0] = Bh32[base];  bh[nb][1] = Bh32[base + 4];
            }
#pragma unroll
            for (int rb = 0; rb < 4; rb++)
#pragma unroll
                for (int nb = 0; nb < 4; nb++)
                    mma_f16(c[rb][nb], ah[rb][0], ah[rb][1], ah[rb][2], ah[rb][3],
                            bh[nb][0], bh[nb][1]);
        }
        __syncthreads();
    }
#pragma unroll
    for (int rb = 0; rb < 4; rb++) {
        int gr0 = row0 + wm * 64 + rb * 16 + g;
#pragma unroll
        for (int nb = 0; nb < 4; nb++) {
            int col = wn * 32 + nb * 8 + 2 * t;
            float* cc = c[rb][nb];
            float2 bv = *(const float2*)(bout + col);
            if (gr0 < N_NODES)
                *(float2*)(out + gr0 * OUTF + col) =
                    make_float2(cc[0] + bv.x, cc[1] + bv.y);
            if (gr0 + 8 < N_NODES)
                *(float2*)(out + (gr0 + 8) * OUTF + col) =
                    make_float2(cc[2] + bv.x, cc[3] + bv.y);
        }
    }
}

// ---------------- launch (fork/join overlap) ----------------
extern "C" void kernel_launch(void* const* d_in, const int* in_sizes, int n_in,
                              void* d_out, int out_size) {
    const float* feat    = (const float*)d_in[0];
    const int*   src     = (const int*)d_in[1];
    const int*   dst     = (const int*)d_in[2];
    const float* Wfc     = (const float*)d_in[3];
    const float* attn_l  = (const float*)d_in[4];
    const float* attn_r  = (const float*)d_in[5];
    const float* Wres    = (const float*)d_in[6];
    const float* biasg   = (const float*)d_in[7];
    const float* gamma   = (const float*)d_in[8];
    const float* beta    = (const float*)d_in[9];
    const float* Wout    = (const float*)d_in[10];
    const float* bout    = (const float*)d_in[11];
    float* out = (float*)d_out;

    static cudaStream_t sB = nullptr;
    static cudaEvent_t evRoot = nullptr, evCsr = nullptr;
    if (sB == nullptr) {
        cudaStreamCreateWithFlags(&sB, cudaStreamNonBlocking);
        cudaEventCreateWithFlags(&evRoot, cudaEventDisableTiming);
        cudaEventCreateWithFlags(&evCsr, cudaEventDisableTiming);
        cudaFuncSetAttribute(gemm1_mma, cudaFuncAttributeMaxDynamicSharedMemorySize, SMEM_G1);
        cudaFuncSetAttribute(gemm2_mma, cudaFuncAttributeMaxDynamicSharedMemorySize, SMEM_G2);
    }

    prep_kernel<<<SCAN_NB + 128 + 64 + 8, 256>>>(Wfc, Wres, Wout, attn_l, attn_r);
    cudaEventRecord(evRoot, 0);

    cudaStreamWaitEvent(sB, evRoot, 0);
    elr_kernel<<<(N_NODES + 7) / 8, 256, 0, sB>>>(feat);
    hist_kernel<<<(N_EDGES + 255) / 256, 256, 0, sB>>>(dst);
    scan1_kernel<<<SCAN_NB, 256, 0, sB>>>();
    scan2_kernel<<<1, 128, 0, sB>>>();
    scan3_kernel<<<SCAN_NB, 256, 0, sB>>>();
    scatter_kernel<<<(N_EDGES + 255) / 256, 256, 0, sB>>>(src, dst);
    cudaEventRecord(evCsr, sB);

    gemm1_mma<<<dim3(2, NROWB), 256, SMEM_G1>>>(feat, biasg);

    cudaStreamWaitEvent(0, evCsr, 0);
    agg_kernel<<<(N_NODES * 2 + 7) / 8, 256>>>();
    bn_kernel<<<BN_BLOCKS, HD>>>(gamma, beta);
    gemm2_mma<<<NROWB, 256, SMEM_G2>>>(bout, out);
}